// round 9
// baseline (speedup 1.0000x reference)
#include <cuda_runtime.h>
#include <cuda_bf16.h>
#include <cstdint>
#include <math.h>

#define NTOK    131072
#define KEXP    16
#define IN_DIM  256
#define OUT_DIM 128
#define TILE_M  128
#define MAX_TILES (NTOK / TILE_M + KEXP - 1)

#define KC      32                 // B k-chunk (floats)
#define NCHUNK  (IN_DIM / KC)      // 8
#define AWORDS  128                // A words per row (256 bf16 = 128 u32), no pad (XOR swizzle)
#define AW      20                 // B row stride words (proven conflict-free)

// ---------------- device scratch ----------------
__device__ int g_counts[KEXP];
__device__ int g_cursor[KEXP];
__device__ int g_perm[NTOK];
__device__ int g_tile_expert[MAX_TILES];
__device__ int g_tile_start[MAX_TILES];
__device__ int g_tile_len[MAX_TILES];
__device__ int g_num_tiles;
__device__ __nv_bfloat16 g_W1b[KEXP * OUT_DIM * IN_DIM];   // [e][n][k] bf16

// ---------------- helpers ----------------
__device__ __forceinline__ uint32_t smem_u32(const void* p) {
    uint32_t a;
    asm("{ .reg .u64 t; cvta.to.shared.u64 t, %1; cvt.u32.u64 %0, t; }" : "=r"(a) : "l"(p));
    return a;
}
__device__ __forceinline__ void cp_async16(uint32_t dst, const void* src) {
    asm volatile("cp.async.cg.shared.global [%0], [%1], 16;" :: "r"(dst), "l"(src) : "memory");
}
#define CP_COMMIT()  asm volatile("cp.async.commit_group;" ::: "memory")
#define CP_WAIT0()   asm volatile("cp.async.wait_group 0;" ::: "memory")
#define CP_WAIT1()   asm volatile("cp.async.wait_group 1;" ::: "memory")

__device__ __forceinline__ uint32_t pack_bf16(float lo, float hi) {
    uint32_t r;
    asm("cvt.rn.bf16x2.f32 %0, %1, %2;" : "=r"(r) : "f"(hi), "f"(lo));
    return r;
}
__device__ __forceinline__ void mma_bf16(float& d0, float& d1, float& d2, float& d3,
                                         uint32_t a0, uint32_t a1, uint32_t a2, uint32_t a3,
                                         uint32_t b0, uint32_t b1) {
    asm volatile(
        "mma.sync.aligned.m16n8k16.row.col.f32.bf16.bf16.f32 "
        "{%0,%1,%2,%3}, {%4,%5,%6,%7}, {%8,%9}, {%0,%1,%2,%3};"
        : "+f"(d0), "+f"(d1), "+f"(d2), "+f"(d3)
        : "r"(a0), "r"(a1), "r"(a2), "r"(a3), "r"(b0), "r"(b1));
}

// ---------------- 1. histogram (4 tokens/thread) ----------------
__global__ void hist_kernel(const int* __restrict__ z) {
    __shared__ int sh[KEXP];
    int tid = threadIdx.x;
    if (tid < KEXP) sh[tid] = 0;
    __syncthreads();
    int i = blockIdx.x * blockDim.x + tid;
    int4 v = ((const int4*)z)[i];
    atomicAdd(&sh[v.x], 1);
    atomicAdd(&sh[v.y], 1);
    atomicAdd(&sh[v.z], 1);
    atomicAdd(&sh[v.w], 1);
    __syncthreads();
    if (tid < KEXP) atomicAdd(&g_counts[tid], sh[tid]);
}

// ---------------- 2. scan + tile table ----------------
__global__ void scan_kernel() {
    __shared__ int s_off[KEXP + 1];
    __shared__ int s_tp[KEXP + 1];
    int tid = threadIdx.x;
    if (tid == 0) {
        int off = 0, tp = 0;
        for (int e = 0; e < KEXP; e++) {
            s_off[e] = off; s_tp[e] = tp;
            g_cursor[e] = off;
            int c = g_counts[e];
            off += c;
            tp += (c + TILE_M - 1) / TILE_M;
        }
        s_off[KEXP] = off; s_tp[KEXP] = tp;
        g_num_tiles = tp;
    }
    __syncthreads();
    int total = s_tp[KEXP];
    for (int idx = tid; idx < total; idx += blockDim.x) {
        int e = 0;
        while (s_tp[e + 1] <= idx) e++;
        int t = idx - s_tp[e];
        g_tile_expert[idx] = e;
        g_tile_start[idx] = s_off[e] + t * TILE_M;
        int rem = g_counts[e] - t * TILE_M;
        g_tile_len[idx] = rem < TILE_M ? rem : TILE_M;
    }
}

// ---------------- 3. W1 transpose [e][k][n] -> [e][n][k] bf16 ----------------
__global__ void w1t_kernel(const float* __restrict__ W1) {
    __shared__ float t[32][33];
    int e  = blockIdx.y;
    int k0 = (blockIdx.x & 7) * 32;
    int n0 = (blockIdx.x >> 3) * 32;
    int tx = threadIdx.x, ty = threadIdx.y;
    const float* src = W1 + ((size_t)e * IN_DIM + k0) * OUT_DIM + n0;
#pragma unroll
    for (int d = 0; d < 32; d += 8)
        t[ty + d][tx] = src[(ty + d) * OUT_DIM + tx];
    __syncthreads();
    __nv_bfloat16* dst = g_W1b + ((size_t)e * OUT_DIM + n0) * IN_DIM + k0;
#pragma unroll
    for (int d = 0; d < 32; d += 8)
        dst[(ty + d) * IN_DIM + tx] = __float2bfloat16_rn(t[tx][ty + d]);
}

// ---------------- 4. scatter (4 tokens/thread) + reset g_counts ----------------
__global__ void scatter_kernel(const int* __restrict__ z) {
    __shared__ int sh_cnt[KEXP];
    __shared__ int sh_base[KEXP];
    int tid = threadIdx.x;
    if (blockIdx.x == 0 && tid < KEXP) g_counts[tid] = 0;
    if (tid < KEXP) sh_cnt[tid] = 0;
    __syncthreads();
    int i = blockIdx.x * blockDim.x + tid;
    int4 v = ((const int4*)z)[i];
    int r0 = atomicAdd(&sh_cnt[v.x], 1);
    int r1 = atomicAdd(&sh_cnt[v.y], 1);
    int r2 = atomicAdd(&sh_cnt[v.z], 1);
    int r3 = atomicAdd(&sh_cnt[v.w], 1);
    __syncthreads();
    if (tid < KEXP) {
        int c = sh_cnt[tid];
        sh_base[tid] = (c > 0) ? atomicAdd(&g_cursor[tid], c) : 0;
    }
    __syncthreads();
    g_perm[sh_base[v.x] + r0] = i * 4 + 0;
    g_perm[sh_base[v.y] + r1] = i * 4 + 1;
    g_perm[sh_base[v.z] + r2] = i * 4 + 2;
    g_perm[sh_base[v.w] + r3] = i * 4 + 3;
}

// ---------------- 5. bf16 HMMA MLP: full-row A tile + chunked B pipeline ----------
struct MlpSmem {
    uint32_t Aw[TILE_M * AWORDS];       // full A tile bf16x2, XOR-swizzled: 65536 B
    uint32_t Bs[3][OUT_DIM][AW];        // B chunks: 30720 B
    float    b1v[OUT_DIM];
    float2   w2v[OUT_DIM];
    float2   pp[TILE_M][2];
};
#define DYN_SMEM ((int)sizeof(MlpSmem))

__global__ __launch_bounds__(256, 2)
void mlp_mma_kernel(const float* __restrict__ x,
                    const float* __restrict__ b1,
                    const float* __restrict__ W2,
                    const float* __restrict__ b2,
                    float* __restrict__ out)
{
    extern __shared__ char dyn[];
    MlpSmem* s = (MlpSmem*)dyn;

    int bid = blockIdx.x;
    if (bid >= g_num_tiles) return;
    int e     = g_tile_expert[bid];
    int start = g_tile_start[bid];
    int len   = g_tile_len[bid];

    int tid = threadIdx.x;
    int wid  = tid >> 5;
    int lane = tid & 31;
    int warp_m = wid >> 1;          // 4 groups of 32 rows
    int warp_n = wid & 1;           // 2 groups of 64 cols
    int r0 = lane >> 2;
    int cq = lane & 3;

    const __nv_bfloat16* W1be = g_W1b + (size_t)e * OUT_DIM * IN_DIM;

    // ---- B staging via cp.async (3-deep) ----
    int bm = tid >> 1;
    int bq = (tid & 1) * 2;
    auto cpB = [&](int c) {
        int buf = c - (c >= 3 ? 3 : 0) - (c >= 6 ? 3 : 0);
        const __nv_bfloat16* srcb = W1be + (size_t)bm * IN_DIM + c * KC;
        cp_async16(smem_u32(&s->Bs[buf][bm][bq * 4]),     srcb + bq * 8);
        cp_async16(smem_u32(&s->Bs[buf][bm][bq * 4 + 4]), srcb + bq * 8 + 8);
        CP_COMMIT();
    };
    cpB(0);
    cpB(1);

    // ---- A full-tile load: row = tid>>1, seg = tid&1; 4 passes x 32 contiguous floats ----
    {
        int row = tid >> 1;
        int seg = tid & 1;
        int rw  = row < len ? row : len - 1;
        int tok = g_perm[start + rw];
        const float4* xr = (const float4*)(x + (size_t)tok * IN_DIM);
        uint32_t xr_sw = (row & 7) << 2;
        uint32_t* arow = &s->Aw[row * AWORDS];
#pragma unroll
        for (int p = 0; p < 4; p++) {
            float4 f[8];
            const float4* src = xr + p * 16 + seg * 8;
#pragma unroll
            for (int j = 0; j < 8; j++) f[j] = src[j];
#pragma unroll
            for (int j = 0; j < 4; j++) {
                uint32_t w = p * 32 + seg * 16 + j * 4;
                uint4 v;
                v.x = pack_bf16(f[2*j].x,   f[2*j].y);
                v.y = pack_bf16(f[2*j].z,   f[2*j].w);
                v.z = pack_bf16(f[2*j+1].x, f[2*j+1].y);
                v.w = pack_bf16(f[2*j+1].z, f[2*j+1].w);
                *(uint4*)&arow[w ^ xr_sw] = v;
            }
        }
    }
    if (tid < OUT_DIM) {
        s->b1v[tid] = b1[e * OUT_DIM + tid];
        s->w2v[tid] = ((const float2*)(W2 + (size_t)e * OUT_DIM * 2))[tid];
    }

    float acc[2][8][4];
#pragma unroll
    for (int mt = 0; mt < 2; mt++)
#pragma unroll
        for (int nt = 0; nt < 8; nt++)
#pragma unroll
            for (int v = 0; v < 4; v++) acc[mt][nt][v] = 0.f;

    int arow0 = warp_m * 32;
    int brow  = warp_n * 64;

#pragma unroll
    for (int i = 0; i < NCHUNK; i++) {
        int buf = i - (i >= 3 ? 3 : 0) - (i >= 6 ? 3 : 0);
        if (i < NCHUNK - 1) { CP_WAIT1(); }
        else                { CP_WAIT0(); }
        __syncthreads();                 // i==0: A tile + b1/w2 visible; else: buf recycled
        if (i + 2 < NCHUNK) cpB(i + 2);

#pragma unroll
        for (int ks = 0; ks < 2; ks++) {
            int kw = i * 16 + ks * 8;    // A word base for this k16
            int kb = ks * 8;             // B word base within chunk
            uint32_t af[2][4];
#pragma unroll
            for (int mt = 0; mt < 2; mt++) {
                int mrA = arow0 + mt * 16 + r0;
                int mrB = mrA + 8;
                uint32_t swA = (mrA & 7) << 2;
                uint32_t swB = (mrB & 7) << 2;
                af[mt][0] = s->Aw[mrA * AWORDS + ((kw + cq)     ^ swA)];
                af[mt][1] = s->Aw[mrB * AWORDS + ((kw + cq)     ^ swB)];
                af[mt][2] = s->Aw[mrA * AWORDS + ((kw + cq + 4) ^ swA)];
                af[mt][3] = s->Aw[mrB * AWORDS + ((kw + cq + 4) ^ swB)];
            }
#pragma unroll
            for (int nt = 0; nt < 8; nt++) {
                uint32_t b0 = s->Bs[buf][brow + nt * 8 + r0][kb + cq    ];
                uint32_t b1f = s->Bs[buf][brow + nt * 8 + r0][kb + cq + 4];
#pragma unroll
                for (int mt = 0; mt < 2; mt++)
                    mma_bf16(acc[mt][nt][0], acc[mt][nt][1], acc[mt][nt][2], acc[mt][nt][3],
                             af[mt][0], af[mt][1], af[mt][2], af[mt][3], b0, b1f);
            }
        }
    }

    // ---- epilogue ----
    float p0[2][2], p1[2][2];
#pragma unroll
    for (int mt = 0; mt < 2; mt++)
#pragma unroll
        for (int h = 0; h < 2; h++) { p0[mt][h] = 0.f; p1[mt][h] = 0.f; }

#pragma unroll
    for (int nt = 0; nt < 8; nt++) {
        int c = warp_n * 64 + nt * 8 + cq * 2;
        float  ba = s->b1v[c], bb = s->b1v[c + 1];
        float2 wa = s->w2v[c], wb = s->w2v[c + 1];
#pragma unroll
        for (int mt = 0; mt < 2; mt++) {
            float h00 = fmaxf(acc[mt][nt][0] + ba, 0.f);
            float h01 = fmaxf(acc[mt][nt][1] + bb, 0.f);
            p0[mt][0] = fmaf(h00, wa.x, fmaf(h01, wb.x, p0[mt][0]));
            p1[mt][0] = fmaf(h00, wa.y, fmaf(h01, wb.y, p1[mt][0]));
            float h10 = fmaxf(acc[mt][nt][2] + ba, 0.f);
            float h11 = fmaxf(acc[mt][nt][3] + bb, 0.f);
            p0[mt][1] = fmaf(h10, wa.x, fmaf(h11, wb.x, p0[mt][1]));
            p1[mt][1] = fmaf(h10, wa.y, fmaf(h11, wb.y, p1[mt][1]));
        }
    }
#pragma unroll
    for (int mt = 0; mt < 2; mt++)
#pragma unroll
        for (int h = 0; h < 2; h++) {
            p0[mt][h] += __shfl_xor_sync(0xFFFFFFFFu, p0[mt][h], 1);
            p1[mt][h] += __shfl_xor_sync(0xFFFFFFFFu, p1[mt][h], 1);
            p0[mt][h] += __shfl_xor_sync(0xFFFFFFFFu, p0[mt][h], 2);
            p1[mt][h] += __shfl_xor_sync(0xFFFFFFFFu, p1[mt][h], 2);
        }
    if (cq == 0) {
#pragma unroll
        for (int mt = 0; mt < 2; mt++)
#pragma unroll
            for (int h = 0; h < 2; h++) {
                int row = warp_m * 32 + mt * 16 + h * 8 + r0;
                s->pp[row][warp_n] = make_float2(p0[mt][h], p1[mt][h]);
            }
    }
    __syncthreads();

    if (tid < TILE_M && tid < len) {
        int otok = g_perm[start + tid];
        float2 a = s->pp[tid][0], b = s->pp[tid][1];
        float l0 = a.x + b.x + b2[e * 2 + 0];
        float l1 = a.y + b.y + b2[e * 2 + 1];
        float mx = fmaxf(l0, l1);
        float e0 = expf(l0 - mx);
        float e1 = expf(l1 - mx);
        float inv = 1.f / (e0 + e1);
        ((float2*)out)[otok] = make_float2(e0 * inv, e1 * inv);
    }
}

// ---------------- launch ----------------
extern "C" void kernel_launch(void* const* d_in, const int* in_sizes, int n_in,
                              void* d_out, int out_size) {
    const float* x  = (const float*)d_in[0];
    const int*   z  = (const int*)d_in[1];
    const float* W1 = (const float*)d_in[2];
    const float* b1 = (const float*)d_in[3];
    const float* W2 = (const float*)d_in[4];
    const float* b2 = (const float*)d_in[5];
    float* out = (float*)d_out;

    cudaFuncSetAttribute(mlp_mma_kernel, cudaFuncAttributeMaxDynamicSharedMemorySize, DYN_SMEM);

    hist_kernel<<<NTOK / 1024, 256>>>(z);
    scan_kernel<<<1, 256>>>();
    w1t_kernel<<<dim3(32, KEXP), dim3(32, 8)>>>(W1);
    scatter_kernel<<<NTOK / 1024, 256>>>(z);
    mlp_mma_kernel<<<MAX_TILES, 256, DYN_SMEM>>>(x, b1, W2, b2, out);
}

// round 10
// speedup vs baseline: 1.2706x; 1.2706x over previous
#include <cuda_runtime.h>
#include <cuda_bf16.h>
#include <cstdint>
#include <math.h>

#define NTOK    131072
#define KEXP    16
#define IN_DIM  256
#define OUT_DIM 128
#define TILE_M  128
#define MAX_TILES (NTOK / TILE_M + KEXP - 1)

#define KC      32                 // k per chunk
#define NCHUNK  (IN_DIM / KC)      // 8
#define AW      20                 // row stride in u32 words (16 data + 4 pad), R4-proven

// ---------------- device scratch ----------------
__device__ int g_counts[KEXP];
__device__ int g_cursor[KEXP];
__device__ int g_perm[NTOK];
__device__ int g_tile_expert[MAX_TILES];
__device__ int g_tile_start[MAX_TILES];
__device__ int g_tile_len[MAX_TILES];
__device__ int g_num_tiles;
// W1 bf16, chunk-major: [e][c][n][k within chunk]  (each (e,c) block = 128*32 bf16 = 8KB contiguous)
__device__ __nv_bfloat16 g_W1b[KEXP * NCHUNK * OUT_DIM * KC];

// ---------------- helpers ----------------
__device__ __forceinline__ uint32_t pack_bf16(float lo, float hi) {
    uint32_t r;
    asm("cvt.rn.bf16x2.f32 %0, %1, %2;" : "=r"(r) : "f"(hi), "f"(lo));
    return r;
}
__device__ __forceinline__ void mma_bf16(float& d0, float& d1, float& d2, float& d3,
                                         uint32_t a0, uint32_t a1, uint32_t a2, uint32_t a3,
                                         uint32_t b0, uint32_t b1) {
    asm volatile(
        "mma.sync.aligned.m16n8k16.row.col.f32.bf16.bf16.f32 "
        "{%0,%1,%2,%3}, {%4,%5,%6,%7}, {%8,%9}, {%0,%1,%2,%3};"
        : "+f"(d0), "+f"(d1), "+f"(d2), "+f"(d3)
        : "r"(a0), "r"(a1), "r"(a2), "r"(a3), "r"(b0), "r"(b1));
}

// ---------------- 1. histogram (4 tokens/thread) ----------------
__global__ void hist_kernel(const int* __restrict__ z) {
    __shared__ int sh[KEXP];
    int tid = threadIdx.x;
    if (tid < KEXP) sh[tid] = 0;
    __syncthreads();
    int i = blockIdx.x * blockDim.x + tid;
    int4 v = ((const int4*)z)[i];
    atomicAdd(&sh[v.x], 1);
    atomicAdd(&sh[v.y], 1);
    atomicAdd(&sh[v.z], 1);
    atomicAdd(&sh[v.w], 1);
    __syncthreads();
    if (tid < KEXP) atomicAdd(&g_counts[tid], sh[tid]);
}

// ---------------- 2. scan + tile table ----------------
__global__ void scan_kernel() {
    __shared__ int s_off[KEXP + 1];
    __shared__ int s_tp[KEXP + 1];
    int tid = threadIdx.x;
    if (tid == 0) {
        int off = 0, tp = 0;
        for (int e = 0; e < KEXP; e++) {
            s_off[e] = off; s_tp[e] = tp;
            g_cursor[e] = off;
            int c = g_counts[e];
            off += c;
            tp += (c + TILE_M - 1) / TILE_M;
        }
        s_off[KEXP] = off; s_tp[KEXP] = tp;
        g_num_tiles = tp;
    }
    __syncthreads();
    int total = s_tp[KEXP];
    for (int idx = tid; idx < total; idx += blockDim.x) {
        int e = 0;
        while (s_tp[e + 1] <= idx) e++;
        int t = idx - s_tp[e];
        g_tile_expert[idx] = e;
        g_tile_start[idx] = s_off[e] + t * TILE_M;
        int rem = g_counts[e] - t * TILE_M;
        g_tile_len[idx] = rem < TILE_M ? rem : TILE_M;
    }
}

// ---------------- 3. W1 transform [e][k][n] -> [e][c][n][k%32] bf16 ----------------
__global__ void w1t_kernel(const float* __restrict__ W1) {
    __shared__ float t[32][33];
    int e  = blockIdx.y;
    int c  = blockIdx.x & 7;           // k chunk
    int k0 = c * 32;
    int n0 = (blockIdx.x >> 3) * 32;
    int tx = threadIdx.x, ty = threadIdx.y;
    const float* src = W1 + ((size_t)e * IN_DIM + k0) * OUT_DIM + n0;
#pragma unroll
    for (int d = 0; d < 32; d += 8)
        t[ty + d][tx] = src[(ty + d) * OUT_DIM + tx];   // t[k_rel][n_rel]
    __syncthreads();
    // dst element (n_rel, k_rel): ((e*8+c)*128 + n0+n_rel)*32 + k_rel; coalesce over tx=k_rel
    __nv_bfloat16* dst = g_W1b + ((size_t)(e * NCHUNK + c) * OUT_DIM + n0) * KC;
#pragma unroll
    for (int d = 0; d < 32; d += 8)
        dst[(ty + d) * KC + tx] = __float2bfloat16_rn(t[tx][ty + d]);
}

// ---------------- 4. scatter (4 tokens/thread) + reset g_counts ----------------
__global__ void scatter_kernel(const int* __restrict__ z) {
    __shared__ int sh_cnt[KEXP];
    __shared__ int sh_base[KEXP];
    int tid = threadIdx.x;
    if (blockIdx.x == 0 && tid < KEXP) g_counts[tid] = 0;
    if (tid < KEXP) sh_cnt[tid] = 0;
    __syncthreads();
    int i = blockIdx.x * blockDim.x + tid;
    int4 v = ((const int4*)z)[i];
    int r0 = atomicAdd(&sh_cnt[v.x], 1);
    int r1 = atomicAdd(&sh_cnt[v.y], 1);
    int r2 = atomicAdd(&sh_cnt[v.z], 1);
    int r3 = atomicAdd(&sh_cnt[v.w], 1);
    __syncthreads();
    if (tid < KEXP) {
        int c = sh_cnt[tid];
        sh_base[tid] = (c > 0) ? atomicAdd(&g_cursor[tid], c) : 0;
    }
    __syncthreads();
    g_perm[sh_base[v.x] + r0] = i * 4 + 0;
    g_perm[sh_base[v.y] + r1] = i * 4 + 1;
    g_perm[sh_base[v.z] + r2] = i * 4 + 2;
    g_perm[sh_base[v.w] + r3] = i * 4 + 3;
}

// ---------------- 5. bf16 HMMA MLP: LDG-coalesced staging, 1 sync/chunk --------------
struct MlpSmem {
    uint32_t As[2][TILE_M][AW];     // 20480 B (packed bf16x2)
    uint32_t Bs[2][OUT_DIM][AW];    // 20480 B
    int    tok[TILE_M];
    float  b1v[OUT_DIM];
    float2 w2v[OUT_DIM];
    float2 pp[TILE_M][2];
};
#define DYN_SMEM ((int)sizeof(MlpSmem))

__global__ __launch_bounds__(256, 2)
void mlp_mma_kernel(const float* __restrict__ x,
                    const float* __restrict__ b1,
                    const float* __restrict__ W2,
                    const float* __restrict__ b2,
                    float* __restrict__ out)
{
    extern __shared__ char dyn[];
    MlpSmem* s = (MlpSmem*)dyn;

    int bid = blockIdx.x;
    if (bid >= g_num_tiles) return;
    int e     = g_tile_expert[bid];
    int start = g_tile_start[bid];
    int len   = g_tile_len[bid];

    int tid = threadIdx.x;
    int wid  = tid >> 5;
    int lane = tid & 31;
    int warp_m = wid >> 1;          // 4 groups of 32 rows
    int warp_n = wid & 1;           // 2 groups of 64 cols
    int r0 = lane >> 2;
    int cq = lane & 3;

    if (tid < TILE_M) {
        s->tok[tid] = g_perm[start + (tid < len ? tid : len - 1)];
        s->b1v[tid] = b1[e * OUT_DIM + tid];
        s->w2v[tid] = ((const float2*)(W2 + (size_t)e * OUT_DIM * 2))[tid];
    }
    __syncthreads();

    // ---- staging geometry ----
    // A: 8 threads/row (coalesced 4 rows per warp-LDG.128); 4 passes of 32 rows
    int arow_s = tid >> 3;          // base row within each pass-group of 32
    int aq     = tid & 7;           // float4 index in the 128B row-chunk
    // B: chunk-contiguous 8KB block; 2 LDG.128 per thread
    const __nv_bfloat16* W1bc = g_W1b + (size_t)e * NCHUNK * OUT_DIM * KC;

    float4 a_reg[4];
    uint4  b_reg[2];
    auto ldgAB = [&](int c) {
#pragma unroll
        for (int p = 0; p < 4; p++) {
            int row = p * 32 + arow_s;
            a_reg[p] = ((const float4*)(x + (size_t)s->tok[row] * IN_DIM + c * KC))[aq];
        }
        const uint4* bsrc = (const uint4*)(W1bc + (size_t)c * OUT_DIM * KC);
        b_reg[0] = bsrc[tid];
        b_reg[1] = bsrc[tid + 256];
    };
    auto stsAB = [&](int c) {
        int buf = c & 1;
#pragma unroll
        for (int p = 0; p < 4; p++) {
            int row = p * 32 + arow_s;
            uint2 w;
            w.x = pack_bf16(a_reg[p].x, a_reg[p].y);
            w.y = pack_bf16(a_reg[p].z, a_reg[p].w);
            *(uint2*)&s->As[buf][row][aq * 2] = w;
        }
        *(uint4*)&s->Bs[buf][tid >> 2][(tid & 3) * 4]        = b_reg[0];
        *(uint4*)&s->Bs[buf][64 + (tid >> 2)][(tid & 3) * 4] = b_reg[1];
    };

    float acc[2][8][4];
#pragma unroll
    for (int mt = 0; mt < 2; mt++)
#pragma unroll
        for (int nt = 0; nt < 8; nt++)
#pragma unroll
            for (int v = 0; v < 4; v++) acc[mt][nt][v] = 0.f;

    ldgAB(0);

    int arow0 = warp_m * 32;
    int brow  = warp_n * 64;

#pragma unroll
    for (int i = 0; i < NCHUNK; i++) {
        int buf = i & 1;
        stsAB(i);
        __syncthreads();                   // chunk i visible; MMA(i-1) done by all
        if (i + 1 < NCHUNK) ldgAB(i + 1);  // latency covered by MMA(i)

#pragma unroll
        for (int ks = 0; ks < 2; ks++) {
            int kb = ks * 8;
            uint32_t af[2][4];
#pragma unroll
            for (int mt = 0; mt < 2; mt++) {
                int mr = arow0 + mt * 16;
                af[mt][0] = s->As[buf][mr + r0    ][kb + cq    ];
                af[mt][1] = s->As[buf][mr + r0 + 8][kb + cq    ];
                af[mt][2] = s->As[buf][mr + r0    ][kb + cq + 4];
                af[mt][3] = s->As[buf][mr + r0 + 8][kb + cq + 4];
            }
#pragma unroll
            for (int nt = 0; nt < 8; nt++) {
                uint32_t b0 = s->Bs[buf][brow + nt * 8 + r0][kb + cq    ];
                uint32_t b1f = s->Bs[buf][brow + nt * 8 + r0][kb + cq + 4];
#pragma unroll
                for (int mt = 0; mt < 2; mt++)
                    mma_bf16(acc[mt][nt][0], acc[mt][nt][1], acc[mt][nt][2], acc[mt][nt][3],
                             af[mt][0], af[mt][1], af[mt][2], af[mt][3], b0, b1f);
            }
        }
    }

    // ---- epilogue ----
    float p0[2][2], p1[2][2];
#pragma unroll
    for (int mt = 0; mt < 2; mt++)
#pragma unroll
        for (int h = 0; h < 2; h++) { p0[mt][h] = 0.f; p1[mt][h] = 0.f; }

#pragma unroll
    for (int nt = 0; nt < 8; nt++) {
        int c = warp_n * 64 + nt * 8 + cq * 2;
        float  ba = s->b1v[c], bb = s->b1v[c + 1];
        float2 wa = s->w2v[c], wb = s->w2v[c + 1];
#pragma unroll
        for (int mt = 0; mt < 2; mt++) {
            float h00 = fmaxf(acc[mt][nt][0] + ba, 0.f);
            float h01 = fmaxf(acc[mt][nt][1] + bb, 0.f);
            p0[mt][0] = fmaf(h00, wa.x, fmaf(h01, wb.x, p0[mt][0]));
            p1[mt][0] = fmaf(h00, wa.y, fmaf(h01, wb.y, p1[mt][0]));
            float h10 = fmaxf(acc[mt][nt][2] + ba, 0.f);
            float h11 = fmaxf(acc[mt][nt][3] + bb, 0.f);
            p0[mt][1] = fmaf(h10, wa.x, fmaf(h11, wb.x, p0[mt][1]));
            p1[mt][1] = fmaf(h10, wa.y, fmaf(h11, wb.y, p1[mt][1]));
        }
    }
#pragma unroll
    for (int mt = 0; mt < 2; mt++)
#pragma unroll
        for (int h = 0; h < 2; h++) {
            p0[mt][h] += __shfl_xor_sync(0xFFFFFFFFu, p0[mt][h], 1);
            p1[mt][h] += __shfl_xor_sync(0xFFFFFFFFu, p1[mt][h], 1);
            p0[mt][h] += __shfl_xor_sync(0xFFFFFFFFu, p0[mt][h], 2);
            p1[mt][h] += __shfl_xor_sync(0xFFFFFFFFu, p1[mt][h], 2);
        }
    if (cq == 0) {
#pragma unroll
        for (int mt = 0; mt < 2; mt++)
#pragma unroll
            for (int h = 0; h < 2; h++) {
                int row = warp_m * 32 + mt * 16 + h * 8 + r0;
                s->pp[row][warp_n] = make_float2(p0[mt][h], p1[mt][h]);
            }
    }
    __syncthreads();

    if (tid < TILE_M && tid < len) {
        float2 a = s->pp[tid][0], b = s->pp[tid][1];
        float l0 = a.x + b.x + b2[e * 2 + 0];
        float l1 = a.y + b.y + b2[e * 2 + 1];
        float mx = fmaxf(l0, l1);
        float e0 = expf(l0 - mx);
        float e1 = expf(l1 - mx);
        float inv = 1.f / (e0 + e1);
        ((float2*)out)[s->tok[tid]] = make_float2(e0 * inv, e1 * inv);
    }
}

// ---------------- launch ----------------
extern "C" void kernel_launch(void* const* d_in, const int* in_sizes, int n_in,
                              void* d_out, int out_size) {
    const float* x  = (const float*)d_in[0];
    const int*   z  = (const int*)d_in[1];
    const float* W1 = (const float*)d_in[2];
    const float* b1 = (const float*)d_in[3];
    const float* W2 = (const float*)d_in[4];
    const float* b2 = (const float*)d_in[5];
    float* out = (float*)d_out;

    cudaFuncSetAttribute(mlp_mma_kernel, cudaFuncAttributeMaxDynamicSharedMemorySize, DYN_SMEM);

    hist_kernel<<<NTOK / 1024, 256>>>(z);
    scan_kernel<<<1, 256>>>();
    w1t_kernel<<<dim3(32, KEXP), dim3(32, 8)>>>(W1);
    scatter_kernel<<<NTOK / 1024, 256>>>(z);
    mlp_mma_kernel<<<MAX_TILES, 256, DYN_SMEM>>>(x, b1, W2, b2, out);
}

// round 11
// speedup vs baseline: 1.5204x; 1.1966x over previous
#include <cuda_runtime.h>
#include <cuda_bf16.h>
#include <cstdint>
#include <math.h>

#define NTOK    131072
#define KEXP    16
#define IN_DIM  256
#define OUT_DIM 128
#define TILE_M  128
#define MAX_TILES (NTOK / TILE_M + KEXP - 1)

#define KC      32                 // k elements per chunk
#define NCHUNK  (IN_DIM / KC)      // 8
#define AF      40                 // A row stride floats (mod 32 == 8 -> conflict-free LDS.64)
#define AW      20                 // B row stride words (proven conflict-free LDS.32)
#define HBLKS   128                // hist blocks inside fused_pre

// ---------------- device scratch ----------------
__device__ int g_counts[KEXP];
__device__ int g_cursor[KEXP];
__device__ int g_perm[NTOK];
__device__ int g_tile_expert[MAX_TILES];
__device__ int g_tile_start[MAX_TILES];
__device__ int g_tile_len[MAX_TILES];
__device__ int g_num_tiles;
__device__ __nv_bfloat16 g_W1b[KEXP * OUT_DIM * IN_DIM];   // [e][n][k] bf16

// ---------------- helpers ----------------
__device__ __forceinline__ uint32_t smem_u32(const void* p) {
    uint32_t a;
    asm("{ .reg .u64 t; cvta.to.shared.u64 t, %1; cvt.u32.u64 %0, t; }" : "=r"(a) : "l"(p));
    return a;
}
__device__ __forceinline__ void cp_async16(uint32_t dst, const void* src) {
    asm volatile("cp.async.cg.shared.global [%0], [%1], 16;" :: "r"(dst), "l"(src) : "memory");
}
#define CP_COMMIT()  asm volatile("cp.async.commit_group;" ::: "memory")
#define CP_WAIT0()   asm volatile("cp.async.wait_group 0;" ::: "memory")
#define CP_WAIT1()   asm volatile("cp.async.wait_group 1;" ::: "memory")

__device__ __forceinline__ uint32_t pack_bf16(float lo, float hi) {
    uint32_t r;
    asm("cvt.rn.bf16x2.f32 %0, %1, %2;" : "=r"(r) : "f"(hi), "f"(lo));
    return r;
}
__device__ __forceinline__ void mma_bf16(float& d0, float& d1, float& d2, float& d3,
                                         uint32_t a0, uint32_t a1, uint32_t a2, uint32_t a3,
                                         uint32_t b0, uint32_t b1) {
    asm volatile(
        "mma.sync.aligned.m16n8k16.row.col.f32.bf16.bf16.f32 "
        "{%0,%1,%2,%3}, {%4,%5,%6,%7}, {%8,%9}, {%0,%1,%2,%3};"
        : "+f"(d0), "+f"(d1), "+f"(d2), "+f"(d3)
        : "r"(a0), "r"(a1), "r"(a2), "r"(a3), "r"(b0), "r"(b1));
}

// ---------------- 1. fused: hist (blocks 0..127) + coalesced W1 transform ----------
// w1t part: block handles (e, 16-row n strip), emits [e][n][k] bf16 with STG.32 coalesced.
__global__ void fused_pre_kernel(const int* __restrict__ z, const float* __restrict__ W1) {
    __shared__ float t[256][17];        // [k][n_rel], 2-way conflict worst case
    __shared__ int sh[KEXP];
    int tid = threadIdx.x;

    if (blockIdx.x < HBLKS) {
        // ---- histogram: 4 tokens/thread ----
        if (tid < KEXP) sh[tid] = 0;
        __syncthreads();
        int i = blockIdx.x * blockDim.x + tid;
        int4 v = ((const int4*)z)[i];
        atomicAdd(&sh[v.x], 1);
        atomicAdd(&sh[v.y], 1);
        atomicAdd(&sh[v.z], 1);
        atomicAdd(&sh[v.w], 1);
        __syncthreads();
        if (tid < KEXP) atomicAdd(&g_counts[tid], sh[tid]);
    } else {
        int idx = blockIdx.x - HBLKS;   // 0..127
        int e     = idx >> 3;           // 0..15
        int strip = idx & 7;            // 0..7
        int n0 = strip * 16;
        // load 256k x 16n strip (float4 over n)
        int kq = tid >> 2;              // 64 k per pass
        int nq = tid & 3;
#pragma unroll
        for (int p = 0; p < 4; p++) {
            int k = p * 64 + kq;
            float4 v = *(const float4*)(W1 + ((size_t)(e * IN_DIM + k) * OUT_DIM) + n0 + nq * 4);
            t[k][nq * 4 + 0] = v.x;
            t[k][nq * 4 + 1] = v.y;
            t[k][nq * 4 + 2] = v.z;
            t[k][nq * 4 + 3] = v.w;
        }
        __syncthreads();
        // write [e][n][k] packed bf16x2, STG.32 fully coalesced over kw
        int kw = tid & 127;
        int nh = tid >> 7;              // 0..1
        uint32_t* dst = (uint32_t*)g_W1b;
#pragma unroll
        for (int p = 0; p < 8; p++) {
            int n = p * 2 + nh;
            uint32_t w = pack_bf16(t[kw * 2][n], t[kw * 2 + 1][n]);
            dst[((size_t)(e * OUT_DIM) + n0 + n) * (IN_DIM / 2) + kw] = w;
        }
    }
}

// ---------------- 2. scan + tile table ----------------
__global__ void scan_kernel() {
    __shared__ int s_off[KEXP + 1];
    __shared__ int s_tp[KEXP + 1];
    int tid = threadIdx.x;
    if (tid == 0) {
        int off = 0, tp = 0;
        for (int e = 0; e < KEXP; e++) {
            s_off[e] = off; s_tp[e] = tp;
            g_cursor[e] = off;
            int c = g_counts[e];
            off += c;
            tp += (c + TILE_M - 1) / TILE_M;
        }
        s_off[KEXP] = off; s_tp[KEXP] = tp;
        g_num_tiles = tp;
    }
    __syncthreads();
    int total = s_tp[KEXP];
    for (int idx = tid; idx < total; idx += blockDim.x) {
        int e = 0;
        while (s_tp[e + 1] <= idx) e++;
        int t = idx - s_tp[e];
        g_tile_expert[idx] = e;
        g_tile_start[idx] = s_off[e] + t * TILE_M;
        int rem = g_counts[e] - t * TILE_M;
        g_tile_len[idx] = rem < TILE_M ? rem : TILE_M;
    }
}

// ---------------- 3. scatter (4 tokens/thread) + reset g_counts ----------------
__global__ void scatter_kernel(const int* __restrict__ z) {
    __shared__ int sh_cnt[KEXP];
    __shared__ int sh_base[KEXP];
    int tid = threadIdx.x;
    if (blockIdx.x == 0 && tid < KEXP) g_counts[tid] = 0;
    if (tid < KEXP) sh_cnt[tid] = 0;
    __syncthreads();
    int i = blockIdx.x * blockDim.x + tid;
    int4 v = ((const int4*)z)[i];
    int r0 = atomicAdd(&sh_cnt[v.x], 1);
    int r1 = atomicAdd(&sh_cnt[v.y], 1);
    int r2 = atomicAdd(&sh_cnt[v.z], 1);
    int r3 = atomicAdd(&sh_cnt[v.w], 1);
    __syncthreads();
    if (tid < KEXP) {
        int c = sh_cnt[tid];
        sh_base[tid] = (c > 0) ? atomicAdd(&g_cursor[tid], c) : 0;
    }
    __syncthreads();
    g_perm[sh_base[v.x] + r0] = i * 4 + 0;
    g_perm[sh_base[v.y] + r1] = i * 4 + 1;
    g_perm[sh_base[v.z] + r2] = i * 4 + 2;
    g_perm[sh_base[v.w] + r3] = i * 4 + 3;
}

// ---------------- 4. bf16 HMMA MLP (EXACT R7) ----------------
struct MlpSmem {
    float    Af[3][TILE_M][AF];         // x chunks fp32: 61440 B
    uint32_t Bs[3][OUT_DIM][AW];        // W1b chunks packed bf16x2: 30720 B
    int    tok[TILE_M];
    float  b1v[OUT_DIM];
    float2 w2v[OUT_DIM];
    float2 pp[TILE_M][2];
};
#define DYN_SMEM ((int)sizeof(MlpSmem))

__global__ __launch_bounds__(256, 2)
void mlp_mma_kernel(const float* __restrict__ x,
                    const float* __restrict__ b1,
                    const float* __restrict__ W2,
                    const float* __restrict__ b2,
                    float* __restrict__ out)
{
    extern __shared__ char dyn[];
    MlpSmem* s = (MlpSmem*)dyn;

    int bid = blockIdx.x;
    if (bid >= g_num_tiles) return;
    int e     = g_tile_expert[bid];
    int start = g_tile_start[bid];
    int len   = g_tile_len[bid];

    int tid = threadIdx.x;
    int wid  = tid >> 5;
    int lane = tid & 31;
    int warp_m = wid >> 1;
    int warp_n = wid & 1;
    int r0 = lane >> 2;
    int cq = lane & 3;

    if (tid < TILE_M) {
        s->tok[tid] = g_perm[start + (tid < len ? tid : len - 1)];
        s->b1v[tid] = b1[e * OUT_DIM + tid];
        s->w2v[tid] = ((const float2*)(W2 + (size_t)e * OUT_DIM * 2))[tid];
    }
    __syncthreads();

    const __nv_bfloat16* W1be = g_W1b + (size_t)e * OUT_DIM * IN_DIM;

    int am = tid >> 1;
    int ahh = (tid & 1) * 16;
    const float* asrc = x + (size_t)s->tok[am] * IN_DIM + ahh;
    int bm = tid >> 1;
    int bq = (tid & 1) * 2;
    auto stage = [&](int c) {
        int buf = c - (c >= 3 ? 3 : 0) - (c >= 6 ? 3 : 0);
        float* ad = &s->Af[buf][am][ahh];
        const float* as = asrc + c * KC;
#pragma unroll
        for (int j = 0; j < 4; j++)
            cp_async16(smem_u32(ad + j * 4), as + j * 4);
        const __nv_bfloat16* srcb = W1be + (size_t)bm * IN_DIM + c * KC;
        cp_async16(smem_u32(&s->Bs[buf][bm][bq * 4]),     srcb + bq * 8);
        cp_async16(smem_u32(&s->Bs[buf][bm][bq * 4 + 4]), srcb + bq * 8 + 8);
        CP_COMMIT();
    };

    float acc[2][8][4];
#pragma unroll
    for (int mt = 0; mt < 2; mt++)
#pragma unroll
        for (int nt = 0; nt < 8; nt++)
#pragma unroll
            for (int v = 0; v < 4; v++) acc[mt][nt][v] = 0.f;

    stage(0);
    stage(1);

    int arow = warp_m * 32;
    int brow = warp_n * 64;

#pragma unroll
    for (int i = 0; i < NCHUNK; i++) {
        int buf = i % 3;
        if (i < NCHUNK - 1) { CP_WAIT1(); }
        else                { CP_WAIT0(); }
        __syncthreads();
        if (i + 2 < NCHUNK) stage(i + 2);

#pragma unroll
        for (int ks = 0; ks < 2; ks++) {
            int kf = ks * 16;
            int kb = ks * 8;
            uint32_t af[2][4];
#pragma unroll
            for (int mt = 0; mt < 2; mt++) {
                int mr = arow + mt * 16;
                float2 f0 = *(const float2*)&s->Af[buf][mr + r0    ][kf + cq * 2];
                float2 f1 = *(const float2*)&s->Af[buf][mr + r0 + 8][kf + cq * 2];
                float2 f2 = *(const float2*)&s->Af[buf][mr + r0    ][kf + 8 + cq * 2];
                float2 f3 = *(const float2*)&s->Af[buf][mr + r0 + 8][kf + 8 + cq * 2];
                af[mt][0] = pack_bf16(f0.x, f0.y);
                af[mt][1] = pack_bf16(f1.x, f1.y);
                af[mt][2] = pack_bf16(f2.x, f2.y);
                af[mt][3] = pack_bf16(f3.x, f3.y);
            }
#pragma unroll
            for (int nt = 0; nt < 8; nt++) {
                uint32_t b0 = s->Bs[buf][brow + nt * 8 + r0][kb + cq    ];
                uint32_t b1f = s->Bs[buf][brow + nt * 8 + r0][kb + cq + 4];
#pragma unroll
                for (int mt = 0; mt < 2; mt++)
                    mma_bf16(acc[mt][nt][0], acc[mt][nt][1], acc[mt][nt][2], acc[mt][nt][3],
                             af[mt][0], af[mt][1], af[mt][2], af[mt][3], b0, b1f);
            }
        }
    }

    float p0[2][2], p1[2][2];
#pragma unroll
    for (int mt = 0; mt < 2; mt++)
#pragma unroll
        for (int h = 0; h < 2; h++) { p0[mt][h] = 0.f; p1[mt][h] = 0.f; }

#pragma unroll
    for (int nt = 0; nt < 8; nt++) {
        int c = warp_n * 64 + nt * 8 + cq * 2;
        float  ba = s->b1v[c], bb = s->b1v[c + 1];
        float2 wa = s->w2v[c], wb = s->w2v[c + 1];
#pragma unroll
        for (int mt = 0; mt < 2; mt++) {
            float h00 = fmaxf(acc[mt][nt][0] + ba, 0.f);
            float h01 = fmaxf(acc[mt][nt][1] + bb, 0.f);
            p0[mt][0] = fmaf(h00, wa.x, fmaf(h01, wb.x, p0[mt][0]));
            p1[mt][0] = fmaf(h00, wa.y, fmaf(h01, wb.y, p1[mt][0]));
            float h10 = fmaxf(acc[mt][nt][2] + ba, 0.f);
            float h11 = fmaxf(acc[mt][nt][3] + bb, 0.f);
            p0[mt][1] = fmaf(h10, wa.x, fmaf(h11, wb.x, p0[mt][1]));
            p1[mt][1] = fmaf(h10, wa.y, fmaf(h11, wb.y, p1[mt][1]));
        }
    }
#pragma unroll
    for (int mt = 0; mt < 2; mt++)
#pragma unroll
        for (int h = 0; h < 2; h++) {
            p0[mt][h] += __shfl_xor_sync(0xFFFFFFFFu, p0[mt][h], 1);
            p1[mt][h] += __shfl_xor_sync(0xFFFFFFFFu, p1[mt][h], 1);
            p0[mt][h] += __shfl_xor_sync(0xFFFFFFFFu, p0[mt][h], 2);
            p1[mt][h] += __shfl_xor_sync(0xFFFFFFFFu, p1[mt][h], 2);
        }
    if (cq == 0) {
#pragma unroll
        for (int mt = 0; mt < 2; mt++)
#pragma unroll
            for (int h = 0; h < 2; h++) {
                int row = warp_m * 32 + mt * 16 + h * 8 + r0;
                s->pp[row][warp_n] = make_float2(p0[mt][h], p1[mt][h]);
            }
    }
    __syncthreads();

    if (tid < TILE_M && tid < len) {
        float2 a = s->pp[tid][0], b = s->pp[tid][1];
        float l0 = a.x + b.x + b2[e * 2 + 0];
        float l1 = a.y + b.y + b2[e * 2 + 1];
        float mx = fmaxf(l0, l1);
        float e0 = expf(l0 - mx);
        float e1 = expf(l1 - mx);
        float inv = 1.f / (e0 + e1);
        ((float2*)out)[s->tok[tid]] = make_float2(e0 * inv, e1 * inv);
    }
}

// ---------------- launch ----------------
extern "C" void kernel_launch(void* const* d_in, const int* in_sizes, int n_in,
                              void* d_out, int out_size) {
    const float* x  = (const float*)d_in[0];
    const int*   z  = (const int*)d_in[1];
    const float* W1 = (const float*)d_in[2];
    const float* b1 = (const float*)d_in[3];
    const float* W2 = (const float*)d_in[4];
    const float* b2 = (const float*)d_in[5];
    float* out = (float*)d_out;

    cudaFuncSetAttribute(mlp_mma_kernel, cudaFuncAttributeMaxDynamicSharedMemorySize, DYN_SMEM);

    fused_pre_kernel<<<HBLKS + 128, 256>>>(z, W1);
    scan_kernel<<<1, 256>>>();
    scatter_kernel<<<NTOK / 1024, 256>>>(z);
    mlp_mma_kernel<<<MAX_TILES, 256, DYN_SMEM>>>(x, b1, W2, b2, out);
}